// round 15
// baseline (speedup 1.0000x reference)
#include <cuda_runtime.h>
#include <cuda_fp16.h>
#include <math.h>
#include <stdint.h>

#define Bb 4
#define Hh 96
#define Ww 96
#define Cc 256
#define Ff 256

// ===================== mma.sync helpers =====================================
__device__ __forceinline__ uint32_t smem_u32(const void* p) {
    uint32_t a;
    asm("{ .reg .u64 t; cvta.to.shared.u64 t, %1; cvt.u32.u64 %0, t; }"
        : "=r"(a) : "l"(p));
    return a;
}
__device__ __forceinline__ void ldsm4(uint32_t* r, uint32_t addr) {
    asm volatile("ldmatrix.sync.aligned.m8n8.x4.shared.b16 {%0,%1,%2,%3}, [%4];"
        : "=r"(r[0]), "=r"(r[1]), "=r"(r[2]), "=r"(r[3]) : "r"(addr));
}
__device__ __forceinline__ void mma_f16(float* d, const uint32_t* a,
                                        uint32_t b0, uint32_t b1) {
    asm volatile(
        "mma.sync.aligned.m16n8k16.row.col.f32.f16.f16.f32 "
        "{%0,%1,%2,%3}, {%4,%5,%6,%7}, {%8,%9}, {%0,%1,%2,%3};"
        : "+f"(d[0]), "+f"(d[1]), "+f"(d[2]), "+f"(d[3])
        : "r"(a[0]), "r"(a[1]), "r"(a[2]), "r"(a[3]), "r"(b0), "r"(b1));
}
__device__ __forceinline__ uint32_t f16x2_of(float v0, float v1) {
    __half2 h = __floats2half2_rn(v0, v1);
    return *(uint32_t*)&h;
}
__device__ __forceinline__ float2 f16x2_tof(uint32_t w) {
    __half2 h = *(__half2*)&w;
    return __half22float2(h);
}
__device__ __forceinline__ void cp16(uint32_t dst, const void* src) {
    asm volatile("cp.async.cg.shared.global [%0], [%1], 16;"
                 :: "r"(dst), "l"(src));
}
__device__ __forceinline__ void cp16z(uint32_t dst, const void* src, int sz) {
    asm volatile("cp.async.cg.shared.global [%0], [%1], 16, %2;"
                 :: "r"(dst), "l"(src), "r"(sz));
}
#define CP_COMMIT() asm volatile("cp.async.commit_group;" ::: "memory")
#define CP_WAIT0()  asm volatile("cp.async.wait_group 0;" ::: "memory")
#define CP_WAIT2()  asm volatile("cp.async.wait_group 2;" ::: "memory")

// ===================== device scratch =======================================
__device__ float g_om[Bb * Hh * Ww * 27];          // dy[9], dx[9], sig(mask)[9]
__device__ uint32_t g_wbh[72 * 256 * 16];          // w_conv fp16 [chunk][f][k/2]
__device__ uint32_t g_wobh[72 * 32 * 16];          // w_off  fp16 [chunk][f][k/2]
#define XWORDS (Bb * Hh * Ww * Cc / 2)
__device__ uint32_t g_xh[XWORDS];                  // x fp16 hi
__device__ uint32_t g_xl[XWORDS];                  // x fp16 lo (residual)

// ===================== prep kernels =========================================
__global__ __launch_bounds__(256) void prep_w_kernel(const float* __restrict__ w_conv)
{
    const int g = blockIdx.x * 256 + threadIdx.x;
    const int kp = g & 15;
    const int f  = (g >> 4) & 255;
    const int chunk = g >> 12;
    const int tap = chunk >> 3, cc = chunk & 7;
    const int c = cc * 32 + 2 * kp;
    const float v0 = w_conv[((size_t)(tap * Cc + c)     * Ff) + f];
    const float v1 = w_conv[((size_t)(tap * Cc + c + 1) * Ff) + f];
    g_wbh[(chunk * 256 + f) * 16 + kp] = f16x2_of(v0, v1);
}

__global__ __launch_bounds__(256) void prep_woff_kernel(const float* __restrict__ w_off)
{
    const int g = blockIdx.x * 256 + threadIdx.x;
    const int kp = g & 15;
    const int f  = (g >> 4) & 31;
    const int chunk = g >> 9;
    const int tap = chunk >> 3, cc = chunk & 7;
    const int c = cc * 32 + 2 * kp;
    float v0 = 0.f, v1 = 0.f;
    if (f < 27) {
        v0 = w_off[((size_t)(tap * Cc + c)     * 27) + f];
        v1 = w_off[((size_t)(tap * Cc + c + 1) * 27) + f];
    }
    g_wobh[(chunk * 32 + f) * 16 + kp] = f16x2_of(v0, v1);
}

__global__ __launch_bounds__(256) void prep_x_kernel(const float* __restrict__ x)
{
    const int i = blockIdx.x * 256 + threadIdx.x;
    const float2 v = ((const float2*)x)[i];
    const uint32_t hw = f16x2_of(v.x, v.y);
    const float2 hf = f16x2_tof(hw);
    g_xh[i] = hw;
    g_xl[i] = f16x2_of(v.x - hf.x, v.y - hf.y);
}

// ===================== Kernel A: offset conv, M=64/CTA, 128 thr, ring4 ======
#define OB_A_HI 0
#define OB_A_LO 5120
#define OB_B_HI 10240
#define OB_BUF  12800
#define OB_SMEM (4 * OB_BUF)     // 51200

__global__ __launch_bounds__(128) void offset_mma_kernel(
    const float* __restrict__ b_off)
{
    extern __shared__ __align__(16) char smem[];
    const uint32_t sb = smem_u32(smem);
    const int tid  = threadIdx.x;
    const int warp = tid >> 5;      // 0..3
    const int lane = tid & 31;
    const int p0 = blockIdx.x * 64;

    float acc[4][4];
#pragma unroll
    for (int nt = 0; nt < 4; nt++)
#pragma unroll
        for (int q = 0; q < 4; q++) acc[nt][q] = 0.f;

    const int spx = tid >> 1;       // 0..63
    const int h16 = tid & 1;
    const int p = p0 + spx;
    const int wpix = p % Ww;
    const int hw_  = p / Ww;
    const int hh = hw_ % Hh;
    const int bimg = hw_ / Hh;

    const uint32_t a_row = (uint32_t)((warp * 16 + (lane & 15)) * 40 + (lane >> 4) * 8);
    const uint32_t b_row = (uint32_t)(((lane & 7) + ((lane >> 4) << 3)) * 40
                                      + ((lane >> 3) & 1) * 8);

    auto stage = [&](int i) {
        const int tap = i >> 3, cc = i & 7;
        const uint32_t bufb = sb + (i & 3) * OB_BUF;
        const int ky = tap / 3, kx = tap % 3;
        const int y  = hh + ky - 1;
        const int xw = wpix + kx - 1;
        const bool valid = (y >= 0) && (y < Hh) && (xw >= 0) && (xw < Ww);
        const int yc = valid ? y : 0, xc = valid ? xw : 0;
        const size_t srcw = ((((size_t)(bimg * Hh + yc) * Ww + xc) * Cc)
                             + cc * 32 + h16 * 16) >> 1;
        const int sz = valid ? 16 : 0;
        const uint32_t dA = bufb + OB_A_HI + spx * 80 + h16 * 32;
        const uint32_t dL = bufb + OB_A_LO + spx * 80 + h16 * 32;
        cp16z(dA,      &g_xh[srcw],     sz);
        cp16z(dA + 16, &g_xh[srcw + 4], sz);
        cp16z(dL,      &g_xl[srcw],     sz);
        cp16z(dL + 16, &g_xl[srcw + 4], sz);
        if (tid < 64) {
            const int row = tid >> 1, bh = tid & 1;
            const size_t s2 = ((size_t)(i * 32 + row) * 16) + bh * 8;
            const uint32_t dbh = bufb + OB_B_HI + row * 80 + bh * 32;
            cp16(dbh,      &g_wobh[s2]);
            cp16(dbh + 16, &g_wobh[s2 + 4]);
        }
        CP_COMMIT();
    };

    stage(0); stage(1); stage(2);
    for (int i = 0; i < 72; i++) {
        CP_WAIT2();
        __syncthreads();
        if (i < 69) stage(i + 3);
        const uint32_t bufb = sb + (i & 3) * OB_BUF;
#pragma unroll
        for (int ks = 0; ks < 2; ks++) {
            uint32_t aH[4], aL[4], bH[2][4];
            ldsm4(aH, bufb + OB_A_HI + (a_row + ks * 16) * 2);
            ldsm4(aL, bufb + OB_A_LO + (a_row + ks * 16) * 2);
#pragma unroll
            for (int np = 0; np < 2; np++)
                ldsm4(bH[np], bufb + OB_B_HI + (b_row + np * 640 + ks * 16) * 2);
#pragma unroll
            for (int nt = 0; nt < 4; nt++) {
                const int np = nt >> 1, s = (nt & 1) * 2;
                mma_f16(acc[nt], aH, bH[np][s], bH[np][s + 1]);
                mma_f16(acc[nt], aL, bH[np][s], bH[np][s + 1]);
            }
        }
    }

    // epilogue: bias + sigmoid(mask) -> g_om
    const int gid = lane >> 2, tig = lane & 3;
    const int row0 = p0 + warp * 16 + gid;
#pragma unroll
    for (int nt = 0; nt < 4; nt++) {
        const int col = nt * 8 + 2 * tig;
#pragma unroll
        for (int e = 0; e < 2; e++) {
            const int c = col + e;
            if (c < 27) {
                const float bo = b_off[c];
                float v0 = acc[nt][e] + bo;
                float v1 = acc[nt][2 + e] + bo;
                if (c >= 18) {
                    v0 = 1.f / (1.f + expf(-v0));
                    v1 = 1.f / (1.f + expf(-v1));
                }
                g_om[(size_t)row0 * 27 + c] = v0;
                g_om[(size_t)(row0 + 8) * 27 + c] = v1;
            }
        }
    }
}

// ===================== Kernel B: deformable GEMM, 512 threads ===============
#define BUF_SZ   40960        // A_HI|A_LO (10240 each) | B_HI (20480)
#define OFF_A_HI 0
#define OFF_A_LO 10240
#define OFF_B_HI 20480
#define OFF_META 81920        // 2 x (MW 2048 | MI 2048)
#define SMEM_SZ  90112

__device__ __forceinline__ void compute_meta(char* smem, int p0, int px,
                                             int tap, int mbuf) {
    const int p = p0 + px;
    const int wpix = p % Ww;
    const int hw_  = p / Ww;
    const int h = hw_ % Hh;
    const int b = hw_ / Hh;
    const float* om = g_om + (size_t)p * 27;
    const float dy = om[tap], dx = om[9 + tap], mask = om[18 + tap];
    const int ky = tap / 3, kx = tap % 3;
    const float ys = (float)(h + ky - 1) + dy;
    const float xs = (float)(wpix + kx - 1) + dx;
    const float y0f = floorf(ys), x0f = floorf(xs);
    const float wy1 = ys - y0f, wx1 = xs - x0f;
    const float wy0 = 1.f - wy1, wx0 = 1.f - wx1;
    const int y0 = (int)y0f, x0i = (int)x0f;
    const int y1 = y0 + 1,   x1i = x0i + 1;
    const bool vy0 = (y0  >= 0) && (y0  < Hh);
    const bool vy1 = (y1  >= 0) && (y1  < Hh);
    const bool vx0 = (x0i >= 0) && (x0i < Ww);
    const bool vx1 = (x1i >= 0) && (x1i < Ww);
    const float c00 = (vy0 && vx0) ? wy0 * wx0 * mask : 0.f;
    const float c01 = (vy0 && vx1) ? wy0 * wx1 * mask : 0.f;
    const float c10 = (vy1 && vx0) ? wy1 * wx0 * mask : 0.f;
    const float c11 = (vy1 && vx1) ? wy1 * wx1 * mask : 0.f;
    const int y0c = min(max(y0, 0), Hh - 1), y1c = min(max(y1, 0), Hh - 1);
    const int x0c = min(max(x0i, 0), Ww - 1), x1c = min(max(x1i, 0), Ww - 1);
    const int r0 = (b * Hh + y0c) * Ww, r1 = (b * Hh + y1c) * Ww;
    char* mb = smem + OFF_META + mbuf * 4096;
    *(float4*)(mb + px * 16) = make_float4(c00, c01, c10, c11);
    // pair-word indices into g_xh (float index / 2)
    *(int4*)(mb + 2048 + px * 16) =
        make_int4(((r0 + x0c) * Cc) >> 1, ((r0 + x1c) * Cc) >> 1,
                  ((r1 + x0c) * Cc) >> 1, ((r1 + x1c) * Cc) >> 1);
}

__global__ __launch_bounds__(512, 1) void dcn_mma_kernel(
    const float* __restrict__ b_conv, float* __restrict__ out)
{
    extern __shared__ __align__(16) char smem[];
    const uint32_t sb = smem_u32(smem);

    const int tid  = threadIdx.x;
    const int warp = tid >> 5;        // 0..15
    const int lane = tid & 31;
    const int wm = warp >> 2;         // 0..3 (M 32)
    const int wn = warp & 3;          // 0..3 (N 64)
    const int p0 = blockIdx.x * 128;

    float acc[2][8][4];
#pragma unroll
    for (int mt = 0; mt < 2; mt++)
#pragma unroll
        for (int nt = 0; nt < 8; nt++)
#pragma unroll
            for (int q = 0; q < 4; q++) acc[mt][nt][q] = 0.f;

    const uint32_t a_row = (uint32_t)((wm * 32 + (lane & 15)) * 40 + (lane >> 4) * 8);
    const uint32_t b_row = (uint32_t)((wn * 64 + (lane & 7) + ((lane >> 4) << 3)) * 40
                                      + ((lane >> 3) & 1) * 8);

    const int spx    = tid >> 2;      // staging pixel (0..127)
    const int cquart = tid & 3;       // staging channel quarter (8 c = 4 pair-words)

    // B copy for chunk i into buffer (i&1): 512 threads, 1 row-half each
    auto stage_b = [&](int i) {
        const int row = tid >> 1, bh = tid & 1;
        const size_t src = ((size_t)(i * 256 + row) * 16) + bh * 8;
        const uint32_t dH = sb + (i & 1) * BUF_SZ + OFF_B_HI + row * 80 + bh * 32;
        cp16(dH,      &g_wbh[src]);
        cp16(dH + 16, &g_wbh[src + 4]);
        CP_COMMIT();
    };
    // convert + STS of prefetched fp16 gather (1 uint4 = 8 channels/thread)
    auto stage_sts = [&](int i, const float4 cw,
                         const uint4 c00, const uint4 c01,
                         const uint4 c10, const uint4 c11) {
        char* buf = smem + (i & 1) * BUF_SZ;
        const uint32_t sbase = (uint32_t)(spx * 80 + cquart * 16);
        uint32_t hw[4], lw[4];
        const uint32_t* w00 = (const uint32_t*)&c00;
        const uint32_t* w01 = (const uint32_t*)&c01;
        const uint32_t* w10 = (const uint32_t*)&c10;
        const uint32_t* w11 = (const uint32_t*)&c11;
#pragma unroll
        for (int j = 0; j < 4; j++) {
            const float2 f00 = f16x2_tof(w00[j]);
            const float2 f01 = f16x2_tof(w01[j]);
            const float2 f10 = f16x2_tof(w10[j]);
            const float2 f11 = f16x2_tof(w11[j]);
            const float v0 = cw.x*f00.x + cw.y*f01.x + cw.z*f10.x + cw.w*f11.x;
            const float v1 = cw.x*f00.y + cw.y*f01.y + cw.z*f10.y + cw.w*f11.y;
            hw[j] = f16x2_of(v0, v1);
            const float2 hf = f16x2_tof(hw[j]);
            lw[j] = f16x2_of(v0 - hf.x, v1 - hf.y);
        }
        *(uint4*)(buf + OFF_A_HI + sbase) = make_uint4(hw[0], hw[1], hw[2], hw[3]);
        *(uint4*)(buf + OFF_A_LO + sbase) = make_uint4(lw[0], lw[1], lw[2], lw[3]);
    };

    // ---- prologue: meta(0), full stage of chunk 0 ----
    if (tid < 128) compute_meta(smem, p0, tid, 0, 0);
    __syncthreads();
    {
        const char* mb = smem + OFF_META;
        const float4 cw = *(const float4*)(mb + spx * 16);
        const int4   ai = *(const int4*)(mb + 2048 + spx * 16);
        const int cgp = cquart * 4;   // chunk 0: cc=0; pair-word offset
        const uint4 c00 = *(const uint4*)(g_xh + ai.x + cgp);
        const uint4 c01 = *(const uint4*)(g_xh + ai.y + cgp);
        const uint4 c10 = *(const uint4*)(g_xh + ai.z + cgp);
        const uint4 c11 = *(const uint4*)(g_xh + ai.w + cgp);
        stage_sts(0, cw, c00, c01, c10, c11);
        stage_b(0);
    }

    for (int i = 0; i < 72; i++) {
        CP_WAIT0();
        __syncthreads();

        // prefetch fp16 gather for i+1 into registers; launch B copy for i+1
        uint4 c00, c01, c10, c11;
        float4 cwn;
        const int inext = i + 1;
        if (inext < 72) {
            const int tapn = inext >> 3, ccn = inext & 7;
            const char* mb = smem + OFF_META + (tapn & 1) * 4096;
            cwn = *(const float4*)(mb + spx * 16);
            const int4 ain = *(const int4*)(mb + 2048 + spx * 16);
            const int cgp = ccn * 16 + cquart * 4;   // pair-word offset
            c00 = *(const uint4*)(g_xh + ain.x + cgp);
            c01 = *(const uint4*)(g_xh + ain.y + cgp);
            c10 = *(const uint4*)(g_xh + ain.z + cgp);
            c11 = *(const uint4*)(g_xh + ain.w + cgp);
            stage_b(inext);
        }

        // ---- MMA burst for chunk i ----
        const uint32_t bufb = sb + (i & 1) * BUF_SZ;
#pragma unroll
        for (int ks = 0; ks < 2; ks++) {
            uint32_t bH[4][4];
#pragma unroll
            for (int np = 0; np < 4; np++)
                ldsm4(bH[np], bufb + OFF_B_HI + (b_row + np * 640 + ks * 16) * 2);
#pragma unroll
            for (int mt = 0; mt < 2; mt++) {
                uint32_t aH[4], aL[4];
                const uint32_t ao = (a_row + mt * 640 + ks * 16) * 2;
                ldsm4(aH, bufb + OFF_A_HI + ao);
                ldsm4(aL, bufb + OFF_A_LO + ao);
#pragma unroll
                for (int nt = 0; nt < 8; nt++) {
                    const int np = nt >> 1, s = (nt & 1) * 2;
                    mma_f16(acc[mt][nt], aH, bH[np][s], bH[np][s + 1]);
                    mma_f16(acc[mt][nt], aL, bH[np][s], bH[np][s + 1]);
                }
            }
        }

        // ---- consume prefetch: bilinear + split + STS into buffer (i+1)&1 --
        if (inext < 72)
            stage_sts(inext, cwn, c00, c01, c10, c11);

        // meta for next tap (readers run after next barrier)
        if ((i & 7) == 6 && i < 64) {
            const int ntap = (i >> 3) + 1;
            if (tid < 128) compute_meta(smem, p0, tid, ntap, ntap & 1);
        }
    }

    // ---- epilogue: + bias, store ----
    const int gid = lane >> 2, tig = lane & 3;
#pragma unroll
    for (int mt = 0; mt < 2; mt++) {
        const int row0 = p0 + wm * 32 + mt * 16 + gid;
#pragma unroll
        for (int nt = 0; nt < 8; nt++) {
            const int f0 = wn * 64 + nt * 8 + 2 * tig;
            const float2 bcv = *(const float2*)(b_conv + f0);
            float2 o0, o1;
            o0.x = acc[mt][nt][0] + bcv.x;
            o0.y = acc[mt][nt][1] + bcv.y;
            o1.x = acc[mt][nt][2] + bcv.x;
            o1.y = acc[mt][nt][3] + bcv.y;
            *(float2*)(out + (size_t)row0 * Ff + f0) = o0;
            *(float2*)(out + (size_t)(row0 + 8) * Ff + f0) = o1;
        }
    }
}

// ===================== launch ==============================================
extern "C" void kernel_launch(void* const* d_in, const int* in_sizes, int n_in,
                              void* d_out, int out_size)
{
    (void)in_sizes; (void)n_in; (void)out_size;
    const float* x      = (const float*)d_in[0];
    const float* w_off  = (const float*)d_in[1];
    const float* b_off  = (const float*)d_in[2];
    const float* w_conv = (const float*)d_in[3];
    const float* b_conv = (const float*)d_in[4];
    float* out = (float*)d_out;

    cudaFuncSetAttribute(dcn_mma_kernel,
                         cudaFuncAttributeMaxDynamicSharedMemorySize, SMEM_SZ);
    cudaFuncSetAttribute(offset_mma_kernel,
                         cudaFuncAttributeMaxDynamicSharedMemorySize, OB_SMEM);

    prep_w_kernel<<<1152, 256>>>(w_conv);
    prep_woff_kernel<<<144, 256>>>(w_off);
    prep_x_kernel<<<XWORDS / 256, 256>>>(x);
    offset_mma_kernel<<<576, 128, OB_SMEM>>>(b_off);
    dcn_mma_kernel<<<288, 512, SMEM_SZ>>>(b_conv, out);
}

// round 16
// speedup vs baseline: 1.1309x; 1.1309x over previous
#include <cuda_runtime.h>
#include <cuda_fp16.h>
#include <math.h>
#include <stdint.h>

#define Bb 4
#define Hh 96
#define Ww 96
#define Cc 256
#define Ff 256

// ===================== mma.sync helpers =====================================
__device__ __forceinline__ uint32_t smem_u32(const void* p) {
    uint32_t a;
    asm("{ .reg .u64 t; cvta.to.shared.u64 t, %1; cvt.u32.u64 %0, t; }"
        : "=r"(a) : "l"(p));
    return a;
}
__device__ __forceinline__ void ldsm4(uint32_t* r, uint32_t addr) {
    asm volatile("ldmatrix.sync.aligned.m8n8.x4.shared.b16 {%0,%1,%2,%3}, [%4];"
        : "=r"(r[0]), "=r"(r[1]), "=r"(r[2]), "=r"(r[3]) : "r"(addr));
}
__device__ __forceinline__ void mma_f16(float* d, const uint32_t* a,
                                        uint32_t b0, uint32_t b1) {
    asm volatile(
        "mma.sync.aligned.m16n8k16.row.col.f32.f16.f16.f32 "
        "{%0,%1,%2,%3}, {%4,%5,%6,%7}, {%8,%9}, {%0,%1,%2,%3};"
        : "+f"(d[0]), "+f"(d[1]), "+f"(d[2]), "+f"(d[3])
        : "r"(a[0]), "r"(a[1]), "r"(a[2]), "r"(a[3]), "r"(b0), "r"(b1));
}
__device__ __forceinline__ uint32_t f16x2_of(float v0, float v1) {
    __half2 h = __floats2half2_rn(v0, v1);
    return *(uint32_t*)&h;
}
__device__ __forceinline__ float2 f16x2_tof(uint32_t w) {
    __half2 h = *(__half2*)&w;
    return __half22float2(h);
}
__device__ __forceinline__ void cp16(uint32_t dst, const void* src) {
    asm volatile("cp.async.cg.shared.global [%0], [%1], 16;"
                 :: "r"(dst), "l"(src));
}
__device__ __forceinline__ void cp16z(uint32_t dst, const void* src, int sz) {
    asm volatile("cp.async.cg.shared.global [%0], [%1], 16, %2;"
                 :: "r"(dst), "l"(src), "r"(sz));
}
#define CP_COMMIT() asm volatile("cp.async.commit_group;" ::: "memory")
#define CP_WAIT0()  asm volatile("cp.async.wait_group 0;" ::: "memory")
#define CP_WAIT1()  asm volatile("cp.async.wait_group 1;" ::: "memory")
#define CP_WAIT2()  asm volatile("cp.async.wait_group 2;" ::: "memory")

// ===================== device scratch =======================================
__device__ float g_om[Bb * Hh * Ww * 27];          // dy[9], dx[9], sig(mask)[9]
__device__ uint32_t g_wbh[72 * 256 * 16];          // w_conv fp16 [chunk][f][k/2]
__device__ uint32_t g_wobh[72 * 32 * 16];          // w_off  fp16 [chunk][f][k/2]
#define XWORDS (Bb * Hh * Ww * Cc / 2)
__device__ uint32_t g_xh[XWORDS];                  // x fp16 hi
__device__ uint32_t g_xl[XWORDS];                  // x fp16 lo (residual)

// ===================== prep kernels =========================================
__global__ __launch_bounds__(256) void prep_w_kernel(const float* __restrict__ w_conv)
{
    const int g = blockIdx.x * 256 + threadIdx.x;
    const int kp = g & 15;
    const int f  = (g >> 4) & 255;
    const int chunk = g >> 12;
    const int tap = chunk >> 3, cc = chunk & 7;
    const int c = cc * 32 + 2 * kp;
    const float v0 = w_conv[((size_t)(tap * Cc + c)     * Ff) + f];
    const float v1 = w_conv[((size_t)(tap * Cc + c + 1) * Ff) + f];
    g_wbh[(chunk * 256 + f) * 16 + kp] = f16x2_of(v0, v1);
}

__global__ __launch_bounds__(256) void prep_woff_kernel(const float* __restrict__ w_off)
{
    const int g = blockIdx.x * 256 + threadIdx.x;
    const int kp = g & 15;
    const int f  = (g >> 4) & 31;
    const int chunk = g >> 9;
    const int tap = chunk >> 3, cc = chunk & 7;
    const int c = cc * 32 + 2 * kp;
    float v0 = 0.f, v1 = 0.f;
    if (f < 27) {
        v0 = w_off[((size_t)(tap * Cc + c)     * 27) + f];
        v1 = w_off[((size_t)(tap * Cc + c + 1) * 27) + f];
    }
    g_wobh[(chunk * 32 + f) * 16 + kp] = f16x2_of(v0, v1);
}

__global__ __launch_bounds__(256) void prep_x_kernel(const float* __restrict__ x)
{
    const int i = blockIdx.x * 256 + threadIdx.x;
    const float2 v = ((const float2*)x)[i];
    const uint32_t hw = f16x2_of(v.x, v.y);
    const float2 hf = f16x2_tof(hw);
    g_xh[i] = hw;
    g_xl[i] = f16x2_of(v.x - hf.x, v.y - hf.y);
}

// ===================== Kernel A: offset conv, 4-stage ring (R13 config) =====
#define OB_A_HI 0
#define OB_A_LO 10240
#define OB_B_HI 20480
#define OB_BUF  23040
#define OB_SMEM (4 * OB_BUF)     // 92160

__global__ __launch_bounds__(256) void offset_mma_kernel(
    const float* __restrict__ b_off)
{
    extern __shared__ __align__(16) char smem[];
    const uint32_t sb = smem_u32(smem);
    const int tid  = threadIdx.x;
    const int warp = tid >> 5;
    const int lane = tid & 31;
    const int p0 = blockIdx.x * 128;

    float acc[4][4];
#pragma unroll
    for (int nt = 0; nt < 4; nt++)
#pragma unroll
        for (int q = 0; q < 4; q++) acc[nt][q] = 0.f;

    const int spx = tid >> 1;
    const int h16 = tid & 1;
    const int p = p0 + spx;
    const int wpix = p % Ww;
    const int hw_  = p / Ww;
    const int hh = hw_ % Hh;
    const int bimg = hw_ / Hh;

    const uint32_t a_row = (uint32_t)((warp * 16 + (lane & 15)) * 40 + (lane >> 4) * 8);
    const uint32_t b_row = (uint32_t)(((lane & 7) + ((lane >> 4) << 3)) * 40
                                      + ((lane >> 3) & 1) * 8);

    auto stage = [&](int i) {
        const int tap = i >> 3, cc = i & 7;
        const uint32_t bufb = sb + (i & 3) * OB_BUF;
        const int ky = tap / 3, kx = tap % 3;
        const int y  = hh + ky - 1;
        const int xw = wpix + kx - 1;
        const bool valid = (y >= 0) && (y < Hh) && (xw >= 0) && (xw < Ww);
        const int yc = valid ? y : 0, xc = valid ? xw : 0;
        const size_t srcw = ((((size_t)(bimg * Hh + yc) * Ww + xc) * Cc)
                             + cc * 32 + h16 * 16) >> 1;
        const int sz = valid ? 16 : 0;
        const uint32_t dA = bufb + OB_A_HI + spx * 80 + h16 * 32;
        const uint32_t dL = bufb + OB_A_LO + spx * 80 + h16 * 32;
        cp16z(dA,      &g_xh[srcw],     sz);
        cp16z(dA + 16, &g_xh[srcw + 4], sz);
        cp16z(dL,      &g_xl[srcw],     sz);
        cp16z(dL + 16, &g_xl[srcw + 4], sz);
        if (tid < 64) {
            const int row = tid >> 1, bh = tid & 1;
            const size_t s2 = ((size_t)(i * 32 + row) * 16) + bh * 8;
            const uint32_t dbh = bufb + OB_B_HI + row * 80 + bh * 32;
            cp16(dbh,      &g_wobh[s2]);
            cp16(dbh + 16, &g_wobh[s2 + 4]);
        }
        CP_COMMIT();
    };

    stage(0); stage(1); stage(2);
    for (int i = 0; i < 72; i++) {
        CP_WAIT2();
        __syncthreads();
        if (i < 69) stage(i + 3);
        const uint32_t bufb = sb + (i & 3) * OB_BUF;
#pragma unroll
        for (int ks = 0; ks < 2; ks++) {
            uint32_t aH[4], aL[4], bH[2][4];
            ldsm4(aH, bufb + OB_A_HI + (a_row + ks * 16) * 2);
            ldsm4(aL, bufb + OB_A_LO + (a_row + ks * 16) * 2);
#pragma unroll
            for (int np = 0; np < 2; np++)
                ldsm4(bH[np], bufb + OB_B_HI + (b_row + np * 640 + ks * 16) * 2);
#pragma unroll
            for (int nt = 0; nt < 4; nt++) {
                const int np = nt >> 1, s = (nt & 1) * 2;
                mma_f16(acc[nt], aH, bH[np][s], bH[np][s + 1]);
                mma_f16(acc[nt], aL, bH[np][s], bH[np][s + 1]);
            }
        }
    }

    // epilogue: bias + sigmoid(mask) -> g_om
    const int gid = lane >> 2, tig = lane & 3;
    const int row0 = p0 + warp * 16 + gid;
#pragma unroll
    for (int nt = 0; nt < 4; nt++) {
        const int col = nt * 8 + 2 * tig;
#pragma unroll
        for (int e = 0; e < 2; e++) {
            const int c = col + e;
            if (c < 27) {
                const float bo = b_off[c];
                float v0 = acc[nt][e] + bo;
                float v1 = acc[nt][2 + e] + bo;
                if (c >= 18) {
                    v0 = 1.f / (1.f + expf(-v0));
                    v1 = 1.f / (1.f + expf(-v1));
                }
                g_om[(size_t)row0 * 27 + c] = v0;
                g_om[(size_t)(row0 + 8) * 27 + c] = v1;
            }
        }
    }
}

// ===================== Kernel B: deformable GEMM, async corner gather =======
// A: 2 x 20480 (HI+LO per buffer). B: 3 x 20480. craw: 2 x 32768. meta: 2 x 4096.
#define OFF_A    0
#define A_BUF    20480
#define OFF_B    40960
#define B_BUF    20480
#define OFF_CRAW 102400
#define CRAW_BUF 32768
#define OFF_META 167936
#define SMEM_SZ  176128

__device__ __forceinline__ void compute_meta(char* smem, int p0, int px,
                                             int tap, int mbuf) {
    const int p = p0 + px;
    const int wpix = p % Ww;
    const int hw_  = p / Ww;
    const int h = hw_ % Hh;
    const int b = hw_ / Hh;
    const float* om = g_om + (size_t)p * 27;
    const float dy = om[tap], dx = om[9 + tap], mask = om[18 + tap];
    const int ky = tap / 3, kx = tap % 3;
    const float ys = (float)(h + ky - 1) + dy;
    const float xs = (float)(wpix + kx - 1) + dx;
    const float y0f = floorf(ys), x0f = floorf(xs);
    const float wy1 = ys - y0f, wx1 = xs - x0f;
    const float wy0 = 1.f - wy1, wx0 = 1.f - wx1;
    const int y0 = (int)y0f, x0i = (int)x0f;
    const int y1 = y0 + 1,   x1i = x0i + 1;
    const bool vy0 = (y0  >= 0) && (y0  < Hh);
    const bool vy1 = (y1  >= 0) && (y1  < Hh);
    const bool vx0 = (x0i >= 0) && (x0i < Ww);
    const bool vx1 = (x1i >= 0) && (x1i < Ww);
    const float c00 = (vy0 && vx0) ? wy0 * wx0 * mask : 0.f;
    const float c01 = (vy0 && vx1) ? wy0 * wx1 * mask : 0.f;
    const float c10 = (vy1 && vx0) ? wy1 * wx0 * mask : 0.f;
    const float c11 = (vy1 && vx1) ? wy1 * wx1 * mask : 0.f;
    const int y0c = min(max(y0, 0), Hh - 1), y1c = min(max(y1, 0), Hh - 1);
    const int x0c = min(max(x0i, 0), Ww - 1), x1c = min(max(x1i, 0), Ww - 1);
    const int r0 = (b * Hh + y0c) * Ww, r1 = (b * Hh + y1c) * Ww;
    char* mb = smem + OFF_META + mbuf * 4096;
    *(float4*)(mb + px * 16) = make_float4(c00, c01, c10, c11);
    // pair-word indices into g_xh (float index / 2)
    *(int4*)(mb + 2048 + px * 16) =
        make_int4(((r0 + x0c) * Cc) >> 1, ((r0 + x1c) * Cc) >> 1,
                  ((r1 + x0c) * Cc) >> 1, ((r1 + x1c) * Cc) >> 1);
}

__global__ __launch_bounds__(512, 1) void dcn_mma_kernel(
    const float* __restrict__ b_conv, float* __restrict__ out)
{
    extern __shared__ __align__(16) char smem[];
    const uint32_t sb = smem_u32(smem);

    const int tid  = threadIdx.x;
    const int warp = tid >> 5;        // 0..15
    const int lane = tid & 31;
    const int wm = warp >> 2;         // 0..3 (M 32)
    const int wn = warp & 3;          // 0..3 (N 64)
    const int p0 = blockIdx.x * 128;

    float acc[2][8][4];
#pragma unroll
    for (int mt = 0; mt < 2; mt++)
#pragma unroll
        for (int nt = 0; nt < 8; nt++)
#pragma unroll
            for (int q = 0; q < 4; q++) acc[mt][nt][q] = 0.f;

    const uint32_t a_row = (uint32_t)((wm * 32 + (lane & 15)) * 40 + (lane >> 4) * 8);
    const uint32_t b_row = (uint32_t)((wn * 64 + (lane & 7) + ((lane >> 4) << 3)) * 40
                                      + ((lane >> 3) & 1) * 8);

    const int spx    = tid >> 2;      // staging pixel (0..127)
    const int cquart = tid & 3;       // channel quarter (8 c = 4 pair-words)

    // issue cp.async for chunk j: 4 corners (hi plane) + B tile rows
    auto stage_cp = [&](int j) {
        const int tapj = j >> 3, ccj = j & 7;
        const char* mb = smem + OFF_META + (tapj & 1) * 4096;
        const int4 ai = *(const int4*)(mb + 2048 + spx * 16);
        const int cgp = ccj * 16 + cquart * 4;
        const uint32_t cb = sb + OFF_CRAW + (j & 1) * CRAW_BUF + tid * 16;
        cp16(cb,         g_xh + ai.x + cgp);
        cp16(cb + 8192,  g_xh + ai.y + cgp);
        cp16(cb + 16384, g_xh + ai.z + cgp);
        cp16(cb + 24576, g_xh + ai.w + cgp);
        const int row = tid >> 1, bh = tid & 1;
        const size_t src = ((size_t)(j * 256 + row) * 16) + bh * 8;
        const uint32_t dH = sb + OFF_B + (j % 3) * B_BUF + row * 80 + bh * 32;
        cp16(dH,      &g_wbh[src]);
        cp16(dH + 16, &g_wbh[src + 4]);
        CP_COMMIT();
    };

    // convert craw(j) -> A(j): interp + fp16 split, STS
    auto convert = [&](int j) {
        const int tapj = j >> 3;
        const char* mb = smem + OFF_META + (tapj & 1) * 4096;
        const float4 cw = *(const float4*)(mb + spx * 16);
        const char* cb = smem + OFF_CRAW + (j & 1) * CRAW_BUF + tid * 16;
        const uint4 c00 = *(const uint4*)(cb);
        const uint4 c01 = *(const uint4*)(cb + 8192);
        const uint4 c10 = *(const uint4*)(cb + 16384);
        const uint4 c11 = *(const uint4*)(cb + 24576);
        char* buf = smem + OFF_A + (j & 1) * A_BUF;
        const uint32_t sbase = (uint32_t)(spx * 80 + cquart * 16);
        uint32_t hw[4], lw[4];
        const uint32_t* w00 = (const uint32_t*)&c00;
        const uint32_t* w01 = (const uint32_t*)&c01;
        const uint32_t* w10 = (const uint32_t*)&c10;
        const uint32_t* w11 = (const uint32_t*)&c11;
#pragma unroll
        for (int q = 0; q < 4; q++) {
            const float2 f00 = f16x2_tof(w00[q]);
            const float2 f01 = f16x2_tof(w01[q]);
            const float2 f10 = f16x2_tof(w10[q]);
            const float2 f11 = f16x2_tof(w11[q]);
            const float v0 = cw.x*f00.x + cw.y*f01.x + cw.z*f10.x + cw.w*f11.x;
            const float v1 = cw.x*f00.y + cw.y*f01.y + cw.z*f10.y + cw.w*f11.y;
            hw[q] = f16x2_of(v0, v1);
            const float2 hf = f16x2_tof(hw[q]);
            lw[q] = f16x2_of(v0 - hf.x, v1 - hf.y);
        }
        *(uint4*)(buf + sbase)         = make_uint4(hw[0], hw[1], hw[2], hw[3]);
        *(uint4*)(buf + 10240 + sbase) = make_uint4(lw[0], lw[1], lw[2], lw[3]);
    };

    // ---- prologue ----
    if (tid < 128) compute_meta(smem, p0, tid, 0, 0);
    __syncthreads();
    stage_cp(0);
    stage_cp(1);
    CP_WAIT1();            // group 0 (chunk 0) complete
    __syncthreads();
    convert(0);

    for (int i = 0; i < 72; i++) {
        __syncthreads();   // A(i), B(i), meta published to all warps

        // ---- MMA burst for chunk i ----
        const uint32_t bufA = sb + OFF_A + (i & 1) * A_BUF;
        const uint32_t bufB = sb + OFF_B + (i % 3) * B_BUF;
#pragma unroll
        for (int ks = 0; ks < 2; ks++) {
            uint32_t bH[4][4];
#pragma unroll
            for (int np = 0; np < 4; np++)
                ldsm4(bH[np], bufB + (b_row + np * 640 + ks * 16) * 2);
#pragma unroll
            for (int mt = 0; mt < 2; mt++) {
                uint32_t aH[4], aL[4];
                const uint32_t ao = (a_row + mt * 640 + ks * 16) * 2;
                ldsm4(aH, bufA + ao);
                ldsm4(aL, bufA + 10240 + ao);
#pragma unroll
                for (int nt = 0; nt < 8; nt++) {
                    const int np = nt >> 1, s = (nt & 1) * 2;
                    mma_f16(acc[mt][nt], aH, bH[np][s], bH[np][s + 1]);
                    mma_f16(acc[mt][nt], aL, bH[np][s], bH[np][s + 1]);
                }
            }
        }

        // ---- convert chunk i+1 (corners arrived), then issue chunk i+2 ----
        if (i + 1 < 72) {
            CP_WAIT0();            // corners(i+1) + B(i+1) complete
            convert(i + 1);
        }
        if (i + 2 < 72) stage_cp(i + 2);

        // meta for next tap, two iterations before first cp use
        if ((i & 7) == 5 && i < 64) {
            const int ntap = (i >> 3) + 1;
            if (tid < 128) compute_meta(smem, p0, tid, ntap, ntap & 1);
        }
    }

    // ---- epilogue: + bias, store ----
    const int gid = lane >> 2, tig = lane & 3;
#pragma unroll
    for (int mt = 0; mt < 2; mt++) {
        const int row0 = p0 + wm * 32 + mt * 16 + gid;
#pragma unroll
        for (int nt = 0; nt < 8; nt++) {
            const int f0 = wn * 64 + nt * 8 + 2 * tig;
            const float2 bcv = *(const float2*)(b_conv + f0);
            float2 o0, o1;
            o0.x = acc[mt][nt][0] + bcv.x;
            o0.y = acc[mt][nt][1] + bcv.y;
            o1.x = acc[mt][nt][2] + bcv.x;
            o1.y = acc[mt][nt][3] + bcv.y;
            *(float2*)(out + (size_t)row0 * Ff + f0) = o0;
            *(float2*)(out + (size_t)(row0 + 8) * Ff + f0) = o1;
        }
    }
}

// ===================== launch ==============================================
extern "C" void kernel_launch(void* const* d_in, const int* in_sizes, int n_in,
                              void* d_out, int out_size)
{
    (void)in_sizes; (void)n_in; (void)out_size;
    const float* x      = (const float*)d_in[0];
    const float* w_off  = (const float*)d_in[1];
    const float* b_off  = (const float*)d_in[2];
    const float* w_conv = (const float*)d_in[3];
    const float* b_conv = (const float*)d_in[4];
    float* out = (float*)d_out;

    cudaFuncSetAttribute(dcn_mma_kernel,
                         cudaFuncAttributeMaxDynamicSharedMemorySize, SMEM_SZ);
    cudaFuncSetAttribute(offset_mma_kernel,
                         cudaFuncAttributeMaxDynamicSharedMemorySize, OB_SMEM);

    prep_w_kernel<<<1152, 256>>>(w_conv);
    prep_woff_kernel<<<144, 256>>>(w_off);
    prep_x_kernel<<<XWORDS / 256, 256>>>(x);
    offset_mma_kernel<<<288, 256, OB_SMEM>>>(b_off);
    dcn_mma_kernel<<<288, 512, SMEM_SZ>>>(b_conv, out);
}

// round 17
// speedup vs baseline: 1.1971x; 1.0586x over previous
#include <cuda_runtime.h>
#include <cuda_fp16.h>
#include <math.h>
#include <stdint.h>

#define Bb 4
#define Hh 96
#define Ww 96
#define Cc 256
#define Ff 256

// ===================== mma.sync helpers =====================================
__device__ __forceinline__ uint32_t smem_u32(const void* p) {
    uint32_t a;
    asm("{ .reg .u64 t; cvta.to.shared.u64 t, %1; cvt.u32.u64 %0, t; }"
        : "=r"(a) : "l"(p));
    return a;
}
__device__ __forceinline__ void ldsm4(uint32_t* r, uint32_t addr) {
    asm volatile("ldmatrix.sync.aligned.m8n8.x4.shared.b16 {%0,%1,%2,%3}, [%4];"
        : "=r"(r[0]), "=r"(r[1]), "=r"(r[2]), "=r"(r[3]) : "r"(addr));
}
__device__ __forceinline__ void mma_f16(float* d, const uint32_t* a,
                                        uint32_t b0, uint32_t b1) {
    asm volatile(
        "mma.sync.aligned.m16n8k16.row.col.f32.f16.f16.f32 "
        "{%0,%1,%2,%3}, {%4,%5,%6,%7}, {%8,%9}, {%0,%1,%2,%3};"
        : "+f"(d[0]), "+f"(d[1]), "+f"(d[2]), "+f"(d[3])
        : "r"(a[0]), "r"(a[1]), "r"(a[2]), "r"(a[3]), "r"(b0), "r"(b1));
}
__device__ __forceinline__ uint32_t f16x2_of(float v0, float v1) {
    __half2 h = __floats2half2_rn(v0, v1);
    return *(uint32_t*)&h;
}
__device__ __forceinline__ float2 f16x2_tof(uint32_t w) {
    __half2 h = *(__half2*)&w;
    return __half22float2(h);
}
__device__ __forceinline__ void cp16(uint32_t dst, const void* src) {
    asm volatile("cp.async.cg.shared.global [%0], [%1], 16;"
                 :: "r"(dst), "l"(src));
}
__device__ __forceinline__ void cp16z(uint32_t dst, const void* src, int sz) {
    asm volatile("cp.async.cg.shared.global [%0], [%1], 16, %2;"
                 :: "r"(dst), "l"(src), "r"(sz));
}
#define CP_COMMIT() asm volatile("cp.async.commit_group;" ::: "memory")
#define CP_WAIT0()  asm volatile("cp.async.wait_group 0;" ::: "memory")
#define CP_WAIT1()  asm volatile("cp.async.wait_group 1;" ::: "memory")
#define CP_WAIT2()  asm volatile("cp.async.wait_group 2;" ::: "memory")

// ===================== device scratch =======================================
__device__ float g_om[Bb * Hh * Ww * 27];          // dy[9], dx[9], sig(mask)[9]
__device__ uint32_t g_wbh[72 * 256 * 16];          // w_conv fp16 [chunk][f][k/2]
__device__ uint32_t g_wobh[72 * 32 * 16];          // w_off  fp16 [chunk][f][k/2]
#define XWORDS (Bb * Hh * Ww * Cc / 2)
__device__ uint32_t g_xh[XWORDS];                  // x fp16 hi
__device__ uint32_t g_xl[XWORDS];                  // x fp16 lo (residual)

// ===================== prep kernels =========================================
__global__ __launch_bounds__(256) void prep_w_kernel(const float* __restrict__ w_conv)
{
    const int g = blockIdx.x * 256 + threadIdx.x;
    const int kp = g & 15;
    const int f  = (g >> 4) & 255;
    const int chunk = g >> 12;
    const int tap = chunk >> 3, cc = chunk & 7;
    const int c = cc * 32 + 2 * kp;
    const float v0 = w_conv[((size_t)(tap * Cc + c)     * Ff) + f];
    const float v1 = w_conv[((size_t)(tap * Cc + c + 1) * Ff) + f];
    g_wbh[(chunk * 256 + f) * 16 + kp] = f16x2_of(v0, v1);
}

__global__ __launch_bounds__(256) void prep_woff_kernel(const float* __restrict__ w_off)
{
    const int g = blockIdx.x * 256 + threadIdx.x;
    const int kp = g & 15;
    const int f  = (g >> 4) & 31;
    const int chunk = g >> 9;
    const int tap = chunk >> 3, cc = chunk & 7;
    const int c = cc * 32 + 2 * kp;
    float v0 = 0.f, v1 = 0.f;
    if (f < 27) {
        v0 = w_off[((size_t)(tap * Cc + c)     * 27) + f];
        v1 = w_off[((size_t)(tap * Cc + c + 1) * 27) + f];
    }
    g_wobh[(chunk * 32 + f) * 16 + kp] = f16x2_of(v0, v1);
}

__global__ __launch_bounds__(256) void prep_x_kernel(const float* __restrict__ x)
{
    const int i = blockIdx.x * 256 + threadIdx.x;
    const float2 v = ((const float2*)x)[i];
    const uint32_t hw = f16x2_of(v.x, v.y);
    const float2 hf = f16x2_tof(hw);
    g_xh[i] = hw;
    g_xl[i] = f16x2_of(v.x - hf.x, v.y - hf.y);
}

// ===================== Kernel A: offset conv, K=64 stages, 1-term A ========
// A: 128 px x 64 c fp16, row stride 72 halves (144B, conflict-free ldsm).
// B: two 32-c sub-tiles (32 f x 16 u32 each, 80B row stride).
#define OB_A    0
#define OB_B    18432            // 128*144
#define OB_BUF  23552            // 18432 + 2*2560
#define OB_SMEM (4 * OB_BUF)     // 94208

__global__ __launch_bounds__(256) void offset_mma_kernel(
    const float* __restrict__ b_off)
{
    extern __shared__ __align__(16) char smem[];
    const uint32_t sb = smem_u32(smem);
    const int tid  = threadIdx.x;
    const int warp = tid >> 5;
    const int lane = tid & 31;
    const int p0 = blockIdx.x * 128;

    float acc[4][4];
#pragma unroll
    for (int nt = 0; nt < 4; nt++)
#pragma unroll
        for (int q = 0; q < 4; q++) acc[nt][q] = 0.f;

    const int spx = tid >> 1;
    const int h16 = tid & 1;            // 32-channel half within the 64-c stage
    const int p = p0 + spx;
    const int wpix = p % Ww;
    const int hw_  = p / Ww;
    const int hh = hw_ % Hh;
    const int bimg = hw_ / Hh;

    // A stride 72 halves
    const uint32_t a_row = (uint32_t)((warp * 16 + (lane & 15)) * 72 + (lane >> 4) * 8);
    const uint32_t b_row = (uint32_t)(((lane & 7) + ((lane >> 4) << 3)) * 40
                                      + ((lane >> 3) & 1) * 8);

    // stage j covers tap = j>>2, channels (j&3)*64 .. +63
    auto stage = [&](int j) {
        const int tap = j >> 2, cc64 = j & 3;
        const uint32_t bufb = sb + (j & 3) * OB_BUF;
        const int ky = tap / 3, kx = tap % 3;
        const int y  = hh + ky - 1;
        const int xw = wpix + kx - 1;
        const bool valid = (y >= 0) && (y < Hh) && (xw >= 0) && (xw < Ww);
        const int yc = valid ? y : 0, xc = valid ? xw : 0;
        const size_t srcw = ((((size_t)(bimg * Hh + yc) * Ww + xc) * Cc)
                             + cc64 * 64 + h16 * 32) >> 1;   // pair-words
        const int sz = valid ? 16 : 0;
        const uint32_t dA = bufb + OB_A + spx * 144 + h16 * 64;
        cp16z(dA,      &g_xh[srcw],      sz);
        cp16z(dA + 16, &g_xh[srcw + 4],  sz);
        cp16z(dA + 32, &g_xh[srcw + 8],  sz);
        cp16z(dA + 48, &g_xh[srcw + 12], sz);
        if (tid < 128) {
            const int sub = tid >> 6;            // which 32-c sub-chunk
            const int row = (tid >> 1) & 31;     // f row
            const int bh  = tid & 1;
            const size_t s2 = ((size_t)((j * 2 + sub) * 32 + row) * 16) + bh * 8;
            const uint32_t dbh = bufb + OB_B + sub * 2560 + row * 80 + bh * 32;
            cp16(dbh,      &g_wobh[s2]);
            cp16(dbh + 16, &g_wobh[s2 + 4]);
        }
        CP_COMMIT();
    };

    stage(0); stage(1); stage(2);
    for (int j = 0; j < 36; j++) {
        CP_WAIT2();
        __syncthreads();
        if (j < 33) stage(j + 3);
        const uint32_t bufb = sb + (j & 3) * OB_BUF;
#pragma unroll
        for (int ks = 0; ks < 4; ks++) {
            const int sub = ks >> 1, ksl = ks & 1;
            uint32_t aH[4], bH[2][4];
            ldsm4(aH, bufb + OB_A + (a_row + ks * 16) * 2);
#pragma unroll
            for (int np = 0; np < 2; np++)
                ldsm4(bH[np], bufb + OB_B + sub * 2560
                              + (b_row + np * 640 + ksl * 16) * 2);
#pragma unroll
            for (int nt = 0; nt < 4; nt++) {
                const int np = nt >> 1, s = (nt & 1) * 2;
                mma_f16(acc[nt], aH, bH[np][s], bH[np][s + 1]);
            }
        }
    }

    // epilogue: bias + sigmoid(mask) -> g_om
    const int gid = lane >> 2, tig = lane & 3;
    const int row0 = p0 + warp * 16 + gid;
#pragma unroll
    for (int nt = 0; nt < 4; nt++) {
        const int col = nt * 8 + 2 * tig;
#pragma unroll
        for (int e = 0; e < 2; e++) {
            const int c = col + e;
            if (c < 27) {
                const float bo = b_off[c];
                float v0 = acc[nt][e] + bo;
                float v1 = acc[nt][2 + e] + bo;
                if (c >= 18) {
                    v0 = 1.f / (1.f + expf(-v0));
                    v1 = 1.f / (1.f + expf(-v1));
                }
                g_om[(size_t)row0 * 27 + c] = v0;
                g_om[(size_t)(row0 + 8) * 27 + c] = v1;
            }
        }
    }
}

// ===================== Kernel B: deformable GEMM, async corner gather =======
// A: 2 x 20480 (HI+LO per buffer). B: 3 x 20480. craw: 2 x 32768. meta: 2 x 4096.
#define OFF_A    0
#define A_BUF    20480
#define OFF_B    40960
#define B_BUF    20480
#define OFF_CRAW 102400
#define CRAW_BUF 32768
#define OFF_META 167936
#define SMEM_SZ  176128

__device__ __forceinline__ void compute_meta(char* smem, int p0, int px,
                                             int tap, int mbuf) {
    const int p = p0 + px;
    const int wpix = p % Ww;
    const int hw_  = p / Ww;
    const int h = hw_ % Hh;
    const int b = hw_ / Hh;
    const float* om = g_om + (size_t)p * 27;
    const float dy = om[tap], dx = om[9 + tap], mask = om[18 + tap];
    const int ky = tap / 3, kx = tap % 3;
    const float ys = (float)(h + ky - 1) + dy;
    const float xs = (float)(wpix + kx - 1) + dx;
    const float y0f = floorf(ys), x0f = floorf(xs);
    const float wy1 = ys - y0f, wx1 = xs - x0f;
    const float wy0 = 1.f - wy1, wx0 = 1.f - wx1;
    const int y0 = (int)y0f, x0i = (int)x0f;
    const int y1 = y0 + 1,   x1i = x0i + 1;
    const bool vy0 = (y0  >= 0) && (y0  < Hh);
    const bool vy1 = (y1  >= 0) && (y1  < Hh);
    const bool vx0 = (x0i >= 0) && (x0i < Ww);
    const bool vx1 = (x1i >= 0) && (x1i < Ww);
    const float c00 = (vy0 && vx0) ? wy0 * wx0 * mask : 0.f;
    const float c01 = (vy0 && vx1) ? wy0 * wx1 * mask : 0.f;
    const float c10 = (vy1 && vx0) ? wy1 * wx0 * mask : 0.f;
    const float c11 = (vy1 && vx1) ? wy1 * wx1 * mask : 0.f;
    const int y0c = min(max(y0, 0), Hh - 1), y1c = min(max(y1, 0), Hh - 1);
    const int x0c = min(max(x0i, 0), Ww - 1), x1c = min(max(x1i, 0), Ww - 1);
    const int r0 = (b * Hh + y0c) * Ww, r1 = (b * Hh + y1c) * Ww;
    char* mb = smem + OFF_META + mbuf * 4096;
    *(float4*)(mb + px * 16) = make_float4(c00, c01, c10, c11);
    *(int4*)(mb + 2048 + px * 16) =
        make_int4(((r0 + x0c) * Cc) >> 1, ((r0 + x1c) * Cc) >> 1,
                  ((r1 + x0c) * Cc) >> 1, ((r1 + x1c) * Cc) >> 1);
}

__global__ __launch_bounds__(512, 1) void dcn_mma_kernel(
    const float* __restrict__ b_conv, float* __restrict__ out)
{
    extern __shared__ __align__(16) char smem[];
    const uint32_t sb = smem_u32(smem);

    const int tid  = threadIdx.x;
    const int warp = tid >> 5;        // 0..15
    const int lane = tid & 31;
    const int wm = warp >> 2;         // 0..3 (M 32)
    const int wn = warp & 3;          // 0..3 (N 64)
    const int p0 = blockIdx.x * 128;

    float acc[2][8][4];
#pragma unroll
    for (int mt = 0; mt < 2; mt++)
#pragma unroll
        for (int nt = 0; nt < 8; nt++)
#pragma unroll
            for (int q = 0; q < 4; q++) acc[mt][nt][q] = 0.f;

    const uint32_t a_row = (uint32_t)((wm * 32 + (lane & 15)) * 40 + (lane >> 4) * 8);
    const uint32_t b_row = (uint32_t)((wn * 64 + (lane & 7) + ((lane >> 4) << 3)) * 40
                                      + ((lane >> 3) & 1) * 8);

    const int spx    = tid >> 2;      // staging pixel (0..127)
    const int cquart = tid & 3;       // channel quarter (8 c = 4 pair-words)

    // issue cp.async for chunk j: 4 corners (hi plane) + B tile rows
    auto stage_cp = [&](int j) {
        const int tapj = j >> 3, ccj = j & 7;
        const char* mb = smem + OFF_META + (tapj & 1) * 4096;
        const int4 ai = *(const int4*)(mb + 2048 + spx * 16);
        const int cgp = ccj * 16 + cquart * 4;
        const uint32_t cb = sb + OFF_CRAW + (j & 1) * CRAW_BUF + tid * 16;
        cp16(cb,         g_xh + ai.x + cgp);
        cp16(cb + 8192,  g_xh + ai.y + cgp);
        cp16(cb + 16384, g_xh + ai.z + cgp);
        cp16(cb + 24576, g_xh + ai.w + cgp);
        const int row = tid >> 1, bh = tid & 1;
        const size_t src = ((size_t)(j * 256 + row) * 16) + bh * 8;
        const uint32_t dH = sb + OFF_B + (j % 3) * B_BUF + row * 80 + bh * 32;
        cp16(dH,      &g_wbh[src]);
        cp16(dH + 16, &g_wbh[src + 4]);
        CP_COMMIT();
    };

    // convert craw(j) -> A(j): interp + fp16 split, STS
    auto convert = [&](int j) {
        const int tapj = j >> 3;
        const char* mb = smem + OFF_META + (tapj & 1) * 4096;
        const float4 cw = *(const float4*)(mb + spx * 16);
        const char* cb = smem + OFF_CRAW + (j & 1) * CRAW_BUF + tid * 16;
        const uint4 c00 = *(const uint4*)(cb);
        const uint4 c01 = *(const uint4*)(cb + 8192);
        const uint4 c10 = *(const uint4*)(cb + 16384);
        const uint4 c11 = *(const uint4*)(cb + 24576);
        char* buf = smem + OFF_A + (j & 1) * A_BUF;
        const uint32_t sbase = (uint32_t)(spx * 80 + cquart * 16);
        uint32_t hw[4], lw[4];
        const uint32_t* w00 = (const uint32_t*)&c00;
        const uint32_t* w01 = (const uint32_t*)&c01;
        const uint32_t* w10 = (const uint32_t*)&c10;
        const uint32_t* w11 = (const uint32_t*)&c11;
#pragma unroll
        for (int q = 0; q < 4; q++) {
            const float2 f00 = f16x2_tof(w00[q]);
            const float2 f01 = f16x2_tof(w01[q]);
            const float2 f10 = f16x2_tof(w10[q]);
            const float2 f11 = f16x2_tof(w11[q]);
            const float v0 = cw.x*f00.x + cw.y*f01.x + cw.z*f10.x + cw.w*f11.x;
            const float v1 = cw.x*f00.y + cw.y*f01.y + cw.z*f10.y + cw.w*f11.y;
            hw[q] = f16x2_of(v0, v1);
            const float2 hf = f16x2_tof(hw[q]);
            lw[q] = f16x2_of(v0 - hf.x, v1 - hf.y);
        }
        *(uint4*)(buf + sbase)         = make_uint4(hw[0], hw[1], hw[2], hw[3]);
        *(uint4*)(buf + 10240 + sbase) = make_uint4(lw[0], lw[1], lw[2], lw[3]);
    };

    // ---- prologue ----
    if (tid < 128) compute_meta(smem, p0, tid, 0, 0);
    __syncthreads();
    stage_cp(0);
    stage_cp(1);
    CP_WAIT1();
    __syncthreads();
    convert(0);

    for (int i = 0; i < 72; i++) {
        __syncthreads();   // A(i), B(i), meta published to all warps

        // ---- MMA burst for chunk i ----
        const uint32_t bufA = sb + OFF_A + (i & 1) * A_BUF;
        const uint32_t bufB = sb + OFF_B + (i % 3) * B_BUF;
#pragma unroll
        for (int ks = 0; ks < 2; ks++) {
            uint32_t bH[4][4];
#pragma unroll
            for (int np = 0; np < 4; np++)
                ldsm4(bH[np], bufB + (b_row + np * 640 + ks * 16) * 2);
#pragma unroll
            for (int mt = 0; mt < 2; mt++) {
                uint32_t aH[4], aL[4];
                const uint32_t ao = (a_row + mt * 640 + ks * 16) * 2;
                ldsm4(aH, bufA + ao);
                ldsm4(aL, bufA + 10240 + ao);
#pragma unroll
                for (int nt = 0; nt < 8; nt++) {
                    const int np = nt >> 1, s = (nt & 1) * 2;
                    mma_f16(acc[mt][nt], aH, bH[np][s], bH[np][s + 1]);
                    mma_f16(acc[mt][nt], aL, bH[np][s], bH[np][s + 1]);
                }
            }
        }

        // ---- convert chunk i+1 (corners arrived), then issue chunk i+2 ----
        if (i + 1 < 72) {
            CP_WAIT0();
            convert(i + 1);
        }
        if (i + 2 < 72) stage_cp(i + 2);

        // meta for next tap, two iterations before first cp use
        if ((i & 7) == 5 && i < 64) {
            const int ntap = (i >> 3) + 1;
            if (tid < 128) compute_meta(smem, p0, tid, ntap, ntap & 1);
        }
    }

    // ---- epilogue: + bias, store ----
    const int gid = lane >> 2, tig = lane & 3;
#pragma unroll
    for (int mt = 0; mt < 2; mt++) {
        const int row0 = p0 + wm * 32 + mt * 16 + gid;
#pragma unroll
        for (int nt = 0; nt < 8; nt++) {
            const int f0 = wn * 64 + nt * 8 + 2 * tig;
            const float2 bcv = *(const float2*)(b_conv + f0);
            float2 o0, o1;
            o0.x = acc[mt][nt][0] + bcv.x;
            o0.y = acc[mt][nt][1] + bcv.y;
            o1.x = acc[mt][nt][2] + bcv.x;
            o1.y = acc[mt][nt][3] + bcv.y;
            *(float2*)(out + (size_t)row0 * Ff + f0) = o0;
            *(float2*)(out + (size_t)(row0 + 8) * Ff + f0) = o1;
        }
    }
}

// ===================== launch ==============================================
extern "C" void kernel_launch(void* const* d_in, const int* in_sizes, int n_in,
                              void* d_out, int out_size)
{
    (void)in_sizes; (void)n_in; (void)out_size;
    const float* x      = (const float*)d_in[0];
    const float* w_off  = (const float*)d_in[1];
    const float* b_off  = (const float*)d_in[2];
    const float* w_conv = (const float*)d_in[3];
    const float* b_conv = (const float*)d_in[4];
    float* out = (float*)d_out;

    cudaFuncSetAttribute(dcn_mma_kernel,
                         cudaFuncAttributeMaxDynamicSharedMemorySize, SMEM_SZ);
    cudaFuncSetAttribute(offset_mma_kernel,
                         cudaFuncAttributeMaxDynamicSharedMemorySize, OB_SMEM);

    prep_w_kernel<<<1152, 256>>>(w_conv);
    prep_woff_kernel<<<144, 256>>>(w_off);
    prep_x_kernel<<<XWORDS / 256, 256>>>(x);
    offset_mma_kernel<<<288, 256, OB_SMEM>>>(b_off);
    dcn_mma_kernel<<<288, 512, SMEM_SZ>>>(b_conv, out);
}